// round 1
// baseline (speedup 1.0000x reference)
#include <cuda_runtime.h>
#include <stdint.h>

// ---------------- static geometry ----------------
#define Bb   2
#define Ss   4096
#define Dd   2048
#define Hh   32
#define HDd  64
#define Tt   32       // tiles
#define TNn  128      // tokens per tile
#define NTH  8
#define NTW  4
#define SCALE 0.125f  // 1/sqrt(64)

#define MM   (Bb*Ss)  // 8192 rows for the projections

// ---------------- scratch (device globals; no allocation allowed) ----------------
__device__ float g_Q[(size_t)MM * Dd];
__device__ float g_K[(size_t)MM * Dd];
__device__ float g_V[(size_t)MM * Dd];
__device__ float g_O[(size_t)MM * Dd];

// ---------------- SGEMM: C[M,N] = A[M,K] @ W[K,N], all row-major fp32 ----------------
#define BM 128
#define BN 128
#define BK 16

__global__ __launch_bounds__(256) void sgemm_kernel(
    const float* __restrict__ A, const float* __restrict__ W,
    float* __restrict__ C, int M, int N, int K)
{
    __shared__ float As[BK][BM + 4];  // transposed A tile
    __shared__ float Bs[BK][BN + 4];

    const int n0 = blockIdx.x * BN;
    const int m0 = blockIdx.y * BM;
    const int tid = threadIdx.x;
    const int tx = tid & 15;   // 0..15 -> 8 output cols each
    const int ty = tid >> 4;   // 0..15 -> 8 output rows each

    float acc[8][8];
#pragma unroll
    for (int i = 0; i < 8; i++)
#pragma unroll
        for (int j = 0; j < 8; j++) acc[i][j] = 0.f;

    for (int k0 = 0; k0 < K; k0 += BK) {
        // A tile: 128 rows x 16 cols = 512 float4 loads (2 per thread)
#pragma unroll
        for (int it = 0; it < 2; it++) {
            int idx = tid + it * 256;
            int row = idx >> 2;          // 0..127
            int c4  = (idx & 3) * 4;     // 0,4,8,12
            float4 v = *reinterpret_cast<const float4*>(
                &A[(size_t)(m0 + row) * K + k0 + c4]);
            As[c4 + 0][row] = v.x;
            As[c4 + 1][row] = v.y;
            As[c4 + 2][row] = v.z;
            As[c4 + 3][row] = v.w;
        }
        // W tile: 16 rows x 128 cols = 512 float4 loads (2 per thread)
#pragma unroll
        for (int it = 0; it < 2; it++) {
            int idx = tid + it * 256;
            int row = idx >> 5;          // 0..15
            int c4  = (idx & 31) * 4;    // 0..124
            float4 v = *reinterpret_cast<const float4*>(
                &W[(size_t)(k0 + row) * N + n0 + c4]);
            *reinterpret_cast<float4*>(&Bs[row][c4]) = v;
        }
        __syncthreads();

#pragma unroll
        for (int k = 0; k < BK; k++) {
            float a[8], b[8];
            float4 a0 = *reinterpret_cast<const float4*>(&As[k][ty * 8]);
            float4 a1 = *reinterpret_cast<const float4*>(&As[k][ty * 8 + 4]);
            float4 b0 = *reinterpret_cast<const float4*>(&Bs[k][tx * 8]);
            float4 b1 = *reinterpret_cast<const float4*>(&Bs[k][tx * 8 + 4]);
            a[0]=a0.x; a[1]=a0.y; a[2]=a0.z; a[3]=a0.w;
            a[4]=a1.x; a[5]=a1.y; a[6]=a1.z; a[7]=a1.w;
            b[0]=b0.x; b[1]=b0.y; b[2]=b0.z; b[3]=b0.w;
            b[4]=b1.x; b[5]=b1.y; b[6]=b1.z; b[7]=b1.w;
#pragma unroll
            for (int i = 0; i < 8; i++)
#pragma unroll
                for (int j = 0; j < 8; j++)
                    acc[i][j] = fmaf(a[i], b[j], acc[i][j]);
        }
        __syncthreads();
    }

#pragma unroll
    for (int i = 0; i < 8; i++) {
        size_t row = (size_t)(m0 + ty * 8 + i);
        float4 v0 = make_float4(acc[i][0], acc[i][1], acc[i][2], acc[i][3]);
        float4 v1 = make_float4(acc[i][4], acc[i][5], acc[i][6], acc[i][7]);
        *reinterpret_cast<float4*>(&C[row * N + n0 + tx * 8])     = v0;
        *reinterpret_cast<float4*>(&C[row * N + n0 + tx * 8 + 4]) = v1;
    }
}

// ---------------- block-sparse sliding-tile attention ----------------
// grid = (T=32, H=32, B=2), block = 128 threads (one per query token in tile)
__global__ __launch_bounds__(128) void attn_kernel(
    const float* __restrict__ Q, const float* __restrict__ Kb,
    const float* __restrict__ Vb, float* __restrict__ O)
{
    // half kv-tile staging: 64 keys x 64 dims, rows padded to 17 float4
    __shared__ float4 Ks[64][17];
    __shared__ float4 Vs[64][17];

    const int t  = blockIdx.x;
    const int h  = blockIdx.y;
    const int b  = blockIdx.z;
    const int tn = threadIdx.x;

    // query token -> flat sequence position
    const int th_i = t >> 2;       // tile row (NTW=4)
    const int tw_i = t & 3;        // tile col
    const int qr = tn >> 4;        // row in 8x16 tile
    const int qc = tn & 15;
    const int sq = (th_i * 8 + qr) * 64 + (tw_i * 16 + qc);

    // load + pre-scale q into registers
    const float* qp = Q + ((size_t)(b * Ss + sq)) * Dd + h * HDd;
    float4 q[16];
#pragma unroll
    for (int i = 0; i < 16; i++) {
        q[i] = reinterpret_cast<const float4*>(qp)[i];
        q[i].x *= SCALE; q[i].y *= SCALE; q[i].z *= SCALE; q[i].w *= SCALE;
    }

    // the 4 kv tiles in the clamped window
    const int ch = min(max(th_i, 1), NTH - 1);
    const int cw = min(max(tw_i, 1), NTW - 1);
    int kvt[4];
    kvt[0] = (ch - 1) * NTW + (cw - 1);
    kvt[1] = (ch - 1) * NTW + cw;
    kvt[2] = ch * NTW + (cw - 1);
    kvt[3] = ch * NTW + cw;

    float m = -1e30f, l = 0.f;
    float4 o[16];
#pragma unroll
    for (int i = 0; i < 16; i++) o[i] = make_float4(0.f, 0.f, 0.f, 0.f);

    for (int kt = 0; kt < 4; kt++) {
        const int ktile = kvt[kt];
        const int kth = ktile >> 2;
        const int ktw = ktile & 3;
        for (int half = 0; half < 2; half++) {
            __syncthreads();
            // cooperative load of 64 K rows + 64 V rows (float4 granularity)
            for (int idx = tn; idx < 64 * 16; idx += 128) {
                int row = idx >> 4;         // 0..63
                int cc  = idx & 15;         // 0..15
                int jj  = half * 64 + row;  // token within kv tile
                int rr  = jj >> 4;
                int ccx = jj & 15;
                int skv = (kth * 8 + rr) * 64 + (ktw * 16 + ccx);
                size_t base = ((size_t)(b * Ss + skv)) * Dd + h * HDd;
                Ks[row][cc] = reinterpret_cast<const float4*>(Kb + base)[cc];
                Vs[row][cc] = reinterpret_cast<const float4*>(Vb + base)[cc];
            }
            __syncthreads();

            for (int j = 0; j < 64; j++) {
                float s = 0.f;
#pragma unroll
                for (int cc = 0; cc < 16; cc++) {
                    float4 kv = Ks[j][cc];
                    s = fmaf(q[cc].x, kv.x, s);
                    s = fmaf(q[cc].y, kv.y, s);
                    s = fmaf(q[cc].z, kv.z, s);
                    s = fmaf(q[cc].w, kv.w, s);
                }
                if (s > m) {
                    float corr = __expf(m - s);   // underflows to 0 on first key
                    l *= corr;
#pragma unroll
                    for (int cc = 0; cc < 16; cc++) {
                        o[cc].x *= corr; o[cc].y *= corr;
                        o[cc].z *= corr; o[cc].w *= corr;
                    }
                    m = s;
                }
                float p = __expf(s - m);
                l += p;
#pragma unroll
                for (int cc = 0; cc < 16; cc++) {
                    float4 vv = Vs[j][cc];
                    o[cc].x = fmaf(p, vv.x, o[cc].x);
                    o[cc].y = fmaf(p, vv.y, o[cc].y);
                    o[cc].z = fmaf(p, vv.z, o[cc].z);
                    o[cc].w = fmaf(p, vv.w, o[cc].w);
                }
            }
        }
    }

    const float inv = 1.f / l;
    float* op = O + ((size_t)(b * Ss + sq)) * Dd + h * HDd;
#pragma unroll
    for (int cc = 0; cc < 16; cc++) {
        float4 v = o[cc];
        v.x *= inv; v.y *= inv; v.z *= inv; v.w *= inv;
        reinterpret_cast<float4*>(op)[cc] = v;
    }
}

// ---------------- launch ----------------
extern "C" void kernel_launch(void* const* d_in, const int* in_sizes, int n_in,
                              void* d_out, int out_size)
{
    const float* X  = (const float*)d_in[0];
    const float* Wq = (const float*)d_in[1];
    const float* Wk = (const float*)d_in[2];
    const float* Wv = (const float*)d_in[3];
    const float* Wo = (const float*)d_in[4];
    float* out = (float*)d_out;

    float *Qp, *Kp, *Vp, *Op;
    cudaGetSymbolAddress((void**)&Qp, g_Q);
    cudaGetSymbolAddress((void**)&Kp, g_K);
    cudaGetSymbolAddress((void**)&Vp, g_V);
    cudaGetSymbolAddress((void**)&Op, g_O);

    dim3 gg(Dd / BN, MM / BM);   // (16, 64)
    sgemm_kernel<<<gg, 256>>>(X, Wq, Qp, MM, Dd, Dd);
    sgemm_kernel<<<gg, 256>>>(X, Wk, Kp, MM, Dd, Dd);
    sgemm_kernel<<<gg, 256>>>(X, Wv, Vp, MM, Dd, Dd);

    dim3 ga(Tt, Hh, Bb);         // (32, 32, 2)
    attn_kernel<<<ga, 128>>>(Qp, Kp, Vp, Op);

    sgemm_kernel<<<gg, 256>>>(Op, Wo, out, MM, Dd, Dd);
}

// round 3
// speedup vs baseline: 1.7870x; 1.7870x over previous
#include <cuda_runtime.h>
#include <stdint.h>

// ---------------- static geometry ----------------
#define Bb   2
#define Ss   4096
#define Dd   2048
#define Hh   32
#define HDd  64
#define Tt   32
#define NTH  8
#define NTW  4
#define SCALE 0.125f  // 1/sqrt(64)

#define MM   (Bb*Ss)  // 8192

// ---------------- scratch ----------------
__device__ float g_Q[(size_t)MM * Dd];
__device__ float g_K[(size_t)MM * Dd];
__device__ float g_V[(size_t)MM * Dd];
__device__ float g_O[(size_t)MM * Dd];

// ---------------- TF32 tensor-core GEMM ----------------
// C[M,N] = A[M,K] @ W[K,N], fp32 in/out, tf32 mma.sync (m16n8k8), fp32 accum.
#define BM 128
#define BN 128
#define BK 32
#define AS_STRIDE 36   // padded k-stride for As  (bank-conflict-free frags)
#define BS_STRIDE 132  // padded n-stride for Bs

__device__ __forceinline__ float to_tf32(float x) {
    uint32_t u;
    asm("cvt.rna.tf32.f32 %0, %1;" : "=r"(u) : "f"(x));
    return __uint_as_float(u);
}

__global__ __launch_bounds__(256) void tf32_gemm_kernel(
    const float* __restrict__ A, const float* __restrict__ W,
    float* __restrict__ C, int M, int N, int K)
{
    __shared__ float As[BM * AS_STRIDE];   // [m][k], 18432 B
    __shared__ float Bs[BK * BS_STRIDE];   // [k][n], 16896 B

    const int n0  = blockIdx.x * BN;
    const int m0  = blockIdx.y * BM;
    const int tid = threadIdx.x;
    const int wid  = tid >> 5;
    const int lane = tid & 31;
    const int g = lane >> 2;   // group id (0..7)
    const int t = lane & 3;    // thread-in-group (0..3)

    const int warp_m = (wid & 3) * 32;  // 4 warps down M
    const int warp_n = (wid >> 2) * 64; // 2 warps across N

    float acc[2][8][4];
#pragma unroll
    for (int i = 0; i < 2; i++)
#pragma unroll
        for (int j = 0; j < 8; j++)
#pragma unroll
            for (int c = 0; c < 4; c++) acc[i][j][c] = 0.f;

    float4 pa[4], pb[4];

    // ---- prologue: load tile 0 ----
#pragma unroll
    for (int it = 0; it < 4; it++) {
        int idx = tid + it * 256;
        pa[it] = *reinterpret_cast<const float4*>(
            &A[(size_t)(m0 + (idx >> 3)) * K + (idx & 7) * 4]);
        pb[it] = *reinterpret_cast<const float4*>(
            &W[(size_t)(idx >> 5) * N + n0 + (idx & 31) * 4]);
    }
#pragma unroll
    for (int it = 0; it < 4; it++) {
        int idx = tid + it * 256;
        {
            int row = idx >> 3, c4 = (idx & 7) * 4;
            float* p = &As[row * AS_STRIDE + c4];
            p[0] = to_tf32(pa[it].x); p[1] = to_tf32(pa[it].y);
            p[2] = to_tf32(pa[it].z); p[3] = to_tf32(pa[it].w);
        }
        {
            int row = idx >> 5, c4 = (idx & 31) * 4;
            float4 v = make_float4(to_tf32(pb[it].x), to_tf32(pb[it].y),
                                   to_tf32(pb[it].z), to_tf32(pb[it].w));
            *reinterpret_cast<float4*>(&Bs[row * BS_STRIDE + c4]) = v;
        }
    }
    __syncthreads();

    const int KT = K / BK;
    for (int kt = 0; kt < KT; kt++) {
        // prefetch next tile into registers (overlaps with mma phase)
        if (kt + 1 < KT) {
            int k0n = (kt + 1) * BK;
#pragma unroll
            for (int it = 0; it < 4; it++) {
                int idx = tid + it * 256;
                pa[it] = *reinterpret_cast<const float4*>(
                    &A[(size_t)(m0 + (idx >> 3)) * K + k0n + (idx & 7) * 4]);
                pb[it] = *reinterpret_cast<const float4*>(
                    &W[(size_t)(k0n + (idx >> 5)) * N + n0 + (idx & 31) * 4]);
            }
        }

        // ---- mma over current smem tile ----
#pragma unroll
        for (int kk = 0; kk < BK; kk += 8) {
            uint32_t af[2][4];
#pragma unroll
            for (int wm = 0; wm < 2; wm++) {
                int mb = warp_m + wm * 16;
                af[wm][0] = __float_as_uint(As[(mb + g)     * AS_STRIDE + kk + t]);
                af[wm][1] = __float_as_uint(As[(mb + g + 8) * AS_STRIDE + kk + t]);
                af[wm][2] = __float_as_uint(As[(mb + g)     * AS_STRIDE + kk + t + 4]);
                af[wm][3] = __float_as_uint(As[(mb + g + 8) * AS_STRIDE + kk + t + 4]);
            }
            uint32_t bf[8][2];
#pragma unroll
            for (int wn = 0; wn < 8; wn++) {
                int nb = warp_n + wn * 8 + g;
                bf[wn][0] = __float_as_uint(Bs[(kk + t)     * BS_STRIDE + nb]);
                bf[wn][1] = __float_as_uint(Bs[(kk + t + 4) * BS_STRIDE + nb]);
            }
#pragma unroll
            for (int wm = 0; wm < 2; wm++)
#pragma unroll
                for (int wn = 0; wn < 8; wn++) {
                    asm volatile(
                        "mma.sync.aligned.m16n8k8.row.col.f32.tf32.tf32.f32 "
                        "{%0,%1,%2,%3},{%4,%5,%6,%7},{%8,%9},{%0,%1,%2,%3};"
                        : "+f"(acc[wm][wn][0]), "+f"(acc[wm][wn][1]),
                          "+f"(acc[wm][wn][2]), "+f"(acc[wm][wn][3])
                        : "r"(af[wm][0]), "r"(af[wm][1]),
                          "r"(af[wm][2]), "r"(af[wm][3]),
                          "r"(bf[wn][0]), "r"(bf[wn][1]));
                }
        }
        __syncthreads();

        // ---- store prefetched tile (with tf32 rounding) ----
        if (kt + 1 < KT) {
#pragma unroll
            for (int it = 0; it < 4; it++) {
                int idx = tid + it * 256;
                {
                    int row = idx >> 3, c4 = (idx & 7) * 4;
                    float* p = &As[row * AS_STRIDE + c4];
                    p[0] = to_tf32(pa[it].x); p[1] = to_tf32(pa[it].y);
                    p[2] = to_tf32(pa[it].z); p[3] = to_tf32(pa[it].w);
                }
                {
                    int row = idx >> 5, c4 = (idx & 31) * 4;
                    float4 v = make_float4(to_tf32(pb[it].x), to_tf32(pb[it].y),
                                           to_tf32(pb[it].z), to_tf32(pb[it].w));
                    *reinterpret_cast<float4*>(&Bs[row * BS_STRIDE + c4]) = v;
                }
            }
            __syncthreads();
        }
    }

    // ---- epilogue ----
#pragma unroll
    for (int wm = 0; wm < 2; wm++) {
        int mb = m0 + warp_m + wm * 16;
#pragma unroll
        for (int wn = 0; wn < 8; wn++) {
            int nb = n0 + warp_n + wn * 8 + 2 * t;
            *reinterpret_cast<float2*>(&C[(size_t)(mb + g) * N + nb]) =
                make_float2(acc[wm][wn][0], acc[wm][wn][1]);
            *reinterpret_cast<float2*>(&C[(size_t)(mb + g + 8) * N + nb]) =
                make_float2(acc[wm][wn][2], acc[wm][wn][3]);
        }
    }
}

// ---------------- block-sparse sliding-tile attention (unchanged) ----------------
__global__ __launch_bounds__(128) void attn_kernel(
    const float* __restrict__ Q, const float* __restrict__ Kb,
    const float* __restrict__ Vb, float* __restrict__ O)
{
    __shared__ float4 Ks[64][17];
    __shared__ float4 Vs[64][17];

    const int tile = blockIdx.x;
    const int h  = blockIdx.y;
    const int b  = blockIdx.z;
    const int tn = threadIdx.x;

    const int th_i = tile >> 2;
    const int tw_i = tile & 3;
    const int qr = tn >> 4;
    const int qc = tn & 15;
    const int sq = (th_i * 8 + qr) * 64 + (tw_i * 16 + qc);

    const float* qp = Q + ((size_t)(b * Ss + sq)) * Dd + h * HDd;
    float4 q[16];
#pragma unroll
    for (int i = 0; i < 16; i++) {
        q[i] = reinterpret_cast<const float4*>(qp)[i];
        q[i].x *= SCALE; q[i].y *= SCALE; q[i].z *= SCALE; q[i].w *= SCALE;
    }

    const int ch = min(max(th_i, 1), NTH - 1);
    const int cw = min(max(tw_i, 1), NTW - 1);
    int kvt[4];
    kvt[0] = (ch - 1) * NTW + (cw - 1);
    kvt[1] = (ch - 1) * NTW + cw;
    kvt[2] = ch * NTW + (cw - 1);
    kvt[3] = ch * NTW + cw;

    float m = -1e30f, l = 0.f;
    float4 o[16];
#pragma unroll
    for (int i = 0; i < 16; i++) o[i] = make_float4(0.f, 0.f, 0.f, 0.f);

    for (int kt = 0; kt < 4; kt++) {
        const int ktile = kvt[kt];
        const int kth = ktile >> 2;
        const int ktw = ktile & 3;
        for (int half = 0; half < 2; half++) {
            __syncthreads();
            for (int idx = tn; idx < 64 * 16; idx += 128) {
                int row = idx >> 4;
                int cc  = idx & 15;
                int jj  = half * 64 + row;
                int rr  = jj >> 4;
                int ccx = jj & 15;
                int skv = (kth * 8 + rr) * 64 + (ktw * 16 + ccx);
                size_t base = ((size_t)(b * Ss + skv)) * Dd + h * HDd;
                Ks[row][cc] = reinterpret_cast<const float4*>(Kb + base)[cc];
                Vs[row][cc] = reinterpret_cast<const float4*>(Vb + base)[cc];
            }
            __syncthreads();

            for (int j = 0; j < 64; j++) {
                float s = 0.f;
#pragma unroll
                for (int cc = 0; cc < 16; cc++) {
                    float4 kv = Ks[j][cc];
                    s = fmaf(q[cc].x, kv.x, s);
                    s = fmaf(q[cc].y, kv.y, s);
                    s = fmaf(q[cc].z, kv.z, s);
                    s = fmaf(q[cc].w, kv.w, s);
                }
                if (s > m) {
                    float corr = __expf(m - s);
                    l *= corr;
#pragma unroll
                    for (int cc = 0; cc < 16; cc++) {
                        o[cc].x *= corr; o[cc].y *= corr;
                        o[cc].z *= corr; o[cc].w *= corr;
                    }
                    m = s;
                }
                float p = __expf(s - m);
                l += p;
#pragma unroll
                for (int cc = 0; cc < 16; cc++) {
                    float4 vv = Vs[j][cc];
                    o[cc].x = fmaf(p, vv.x, o[cc].x);
                    o[cc].y = fmaf(p, vv.y, o[cc].y);
                    o[cc].z = fmaf(p, vv.z, o[cc].z);
                    o[cc].w = fmaf(p, vv.w, o[cc].w);
                }
            }
        }
    }

    const float inv = 1.f / l;
    float* op = O + ((size_t)(b * Ss + sq)) * Dd + h * HDd;
#pragma unroll
    for (int cc = 0; cc < 16; cc++) {
        float4 v = o[cc];
        v.x *= inv; v.y *= inv; v.z *= inv; v.w *= inv;
        reinterpret_cast<float4*>(op)[cc] = v;
    }
}

// ---------------- launch ----------------
extern "C" void kernel_launch(void* const* d_in, const int* in_sizes, int n_in,
                              void* d_out, int out_size)
{
    const float* X  = (const float*)d_in[0];
    const float* Wq = (const float*)d_in[1];
    const float* Wk = (const float*)d_in[2];
    const float* Wv = (const float*)d_in[3];
    const float* Wo = (const float*)d_in[4];
    float* out = (float*)d_out;

    float *Qp, *Kp, *Vp, *Op;
    cudaGetSymbolAddress((void**)&Qp, g_Q);
    cudaGetSymbolAddress((void**)&Kp, g_K);
    cudaGetSymbolAddress((void**)&Vp, g_V);
    cudaGetSymbolAddress((void**)&Op, g_O);

    dim3 gg(Dd / BN, MM / BM);   // (16, 64)
    tf32_gemm_kernel<<<gg, 256>>>(X, Wq, Qp, MM, Dd, Dd);
    tf32_gemm_kernel<<<gg, 256>>>(X, Wk, Kp, MM, Dd, Dd);
    tf32_gemm_kernel<<<gg, 256>>>(X, Wv, Vp, MM, Dd, Dd);

    dim3 ga(Tt, Hh, Bb);
    attn_kernel<<<ga, 128>>>(Qp, Kp, Vp, Op);

    tf32_gemm_kernel<<<gg, 256>>>(Op, Wo, out, MM, Dd, Dd);
}

// round 4
// speedup vs baseline: 2.3392x; 1.3091x over previous
#include <cuda_runtime.h>
#include <stdint.h>

// ---------------- static geometry ----------------
#define Bb   2
#define Ss   4096
#define Dd   2048
#define Hh   32
#define HDd  64
#define Tt   32
#define NTH  8
#define NTW  4
#define SCALE 0.125f  // 1/sqrt(64)

#define MM   (Bb*Ss)  // 8192

// ---------------- scratch ----------------
__device__ float g_Q[(size_t)MM * Dd];
__device__ float g_K[(size_t)MM * Dd];
__device__ float g_V[(size_t)MM * Dd];
__device__ float g_O[(size_t)MM * Dd];

__device__ __forceinline__ uint32_t tf32_bits(float x) {
    uint32_t u;
    asm("cvt.rna.tf32.f32 %0, %1;" : "=r"(u) : "f"(x));
    return u;
}
__device__ __forceinline__ float to_tf32(float x) {
    return __uint_as_float(tf32_bits(x));
}

// ---------------- TF32 tensor-core GEMM (unchanged from round 3) ----------------
#define BM 128
#define BN 128
#define BK 32
#define AS_STRIDE 36
#define BS_STRIDE 132

__global__ __launch_bounds__(256) void tf32_gemm_kernel(
    const float* __restrict__ A, const float* __restrict__ W,
    float* __restrict__ C, int M, int N, int K)
{
    __shared__ float As[BM * AS_STRIDE];
    __shared__ float Bs[BK * BS_STRIDE];

    const int n0  = blockIdx.x * BN;
    const int m0  = blockIdx.y * BM;
    const int tid = threadIdx.x;
    const int wid  = tid >> 5;
    const int lane = tid & 31;
    const int g = lane >> 2;
    const int t = lane & 3;

    const int warp_m = (wid & 3) * 32;
    const int warp_n = (wid >> 2) * 64;

    float acc[2][8][4];
#pragma unroll
    for (int i = 0; i < 2; i++)
#pragma unroll
        for (int j = 0; j < 8; j++)
#pragma unroll
            for (int c = 0; c < 4; c++) acc[i][j][c] = 0.f;

    float4 pa[4], pb[4];

#pragma unroll
    for (int it = 0; it < 4; it++) {
        int idx = tid + it * 256;
        pa[it] = *reinterpret_cast<const float4*>(
            &A[(size_t)(m0 + (idx >> 3)) * K + (idx & 7) * 4]);
        pb[it] = *reinterpret_cast<const float4*>(
            &W[(size_t)(idx >> 5) * N + n0 + (idx & 31) * 4]);
    }
#pragma unroll
    for (int it = 0; it < 4; it++) {
        int idx = tid + it * 256;
        {
            int row = idx >> 3, c4 = (idx & 7) * 4;
            float* p = &As[row * AS_STRIDE + c4];
            p[0] = to_tf32(pa[it].x); p[1] = to_tf32(pa[it].y);
            p[2] = to_tf32(pa[it].z); p[3] = to_tf32(pa[it].w);
        }
        {
            int row = idx >> 5, c4 = (idx & 31) * 4;
            float4 v = make_float4(to_tf32(pb[it].x), to_tf32(pb[it].y),
                                   to_tf32(pb[it].z), to_tf32(pb[it].w));
            *reinterpret_cast<float4*>(&Bs[row * BS_STRIDE + c4]) = v;
        }
    }
    __syncthreads();

    const int KT = K / BK;
    for (int kt = 0; kt < KT; kt++) {
        if (kt + 1 < KT) {
            int k0n = (kt + 1) * BK;
#pragma unroll
            for (int it = 0; it < 4; it++) {
                int idx = tid + it * 256;
                pa[it] = *reinterpret_cast<const float4*>(
                    &A[(size_t)(m0 + (idx >> 3)) * K + k0n + (idx & 7) * 4]);
                pb[it] = *reinterpret_cast<const float4*>(
                    &W[(size_t)(k0n + (idx >> 5)) * N + n0 + (idx & 31) * 4]);
            }
        }

#pragma unroll
        for (int kk = 0; kk < BK; kk += 8) {
            uint32_t af[2][4];
#pragma unroll
            for (int wm = 0; wm < 2; wm++) {
                int mb = warp_m + wm * 16;
                af[wm][0] = __float_as_uint(As[(mb + g)     * AS_STRIDE + kk + t]);
                af[wm][1] = __float_as_uint(As[(mb + g + 8) * AS_STRIDE + kk + t]);
                af[wm][2] = __float_as_uint(As[(mb + g)     * AS_STRIDE + kk + t + 4]);
                af[wm][3] = __float_as_uint(As[(mb + g + 8) * AS_STRIDE + kk + t + 4]);
            }
            uint32_t bf[8][2];
#pragma unroll
            for (int wn = 0; wn < 8; wn++) {
                int nb = warp_n + wn * 8 + g;
                bf[wn][0] = __float_as_uint(Bs[(kk + t)     * BS_STRIDE + nb]);
                bf[wn][1] = __float_as_uint(Bs[(kk + t + 4) * BS_STRIDE + nb]);
            }
#pragma unroll
            for (int wm = 0; wm < 2; wm++)
#pragma unroll
                for (int wn = 0; wn < 8; wn++) {
                    asm volatile(
                        "mma.sync.aligned.m16n8k8.row.col.f32.tf32.tf32.f32 "
                        "{%0,%1,%2,%3},{%4,%5,%6,%7},{%8,%9},{%0,%1,%2,%3};"
                        : "+f"(acc[wm][wn][0]), "+f"(acc[wm][wn][1]),
                          "+f"(acc[wm][wn][2]), "+f"(acc[wm][wn][3])
                        : "r"(af[wm][0]), "r"(af[wm][1]),
                          "r"(af[wm][2]), "r"(af[wm][3]),
                          "r"(bf[wn][0]), "r"(bf[wn][1]));
                }
        }
        __syncthreads();

        if (kt + 1 < KT) {
#pragma unroll
            for (int it = 0; it < 4; it++) {
                int idx = tid + it * 256;
                {
                    int row = idx >> 3, c4 = (idx & 7) * 4;
                    float* p = &As[row * AS_STRIDE + c4];
                    p[0] = to_tf32(pa[it].x); p[1] = to_tf32(pa[it].y);
                    p[2] = to_tf32(pa[it].z); p[3] = to_tf32(pa[it].w);
                }
                {
                    int row = idx >> 5, c4 = (idx & 31) * 4;
                    float4 v = make_float4(to_tf32(pb[it].x), to_tf32(pb[it].y),
                                           to_tf32(pb[it].z), to_tf32(pb[it].w));
                    *reinterpret_cast<float4*>(&Bs[row * BS_STRIDE + c4]) = v;
                }
            }
            __syncthreads();
        }
    }

#pragma unroll
    for (int wm = 0; wm < 2; wm++) {
        int mb = m0 + warp_m + wm * 16;
#pragma unroll
        for (int wn = 0; wn < 8; wn++) {
            int nb = n0 + warp_n + wn * 8 + 2 * t;
            *reinterpret_cast<float2*>(&C[(size_t)(mb + g) * N + nb]) =
                make_float2(acc[wm][wn][0], acc[wm][wn][1]);
            *reinterpret_cast<float2*>(&C[(size_t)(mb + g + 8) * N + nb]) =
                make_float2(acc[wm][wn][2], acc[wm][wn][3]);
        }
    }
}

// ---------------- tensor-core block-sparse sliding-tile attention ----------------
// One CTA (256 thr, 8 warps) per (b,h,t). Warp w owns query rows [16w,16w+16).
// 8 chunks of 64 keys. S = Q K^T and O += P V on mma.sync tf32.
#define KS_STRIDE 68
#define VS_STRIDE 72

__global__ __launch_bounds__(256, 2) void attn_mma_kernel(
    const float* __restrict__ Q, const float* __restrict__ Kb,
    const float* __restrict__ Vb, float* __restrict__ O)
{
    __shared__ float Ks[64 * KS_STRIDE];  // [key][hd], tf32 values
    __shared__ float Vs[64 * VS_STRIDE];  // [key][hd], tf32 values

    const int tile = blockIdx.x;
    const int h    = blockIdx.y;
    const int b    = blockIdx.z;
    const int tid  = threadIdx.x;
    const int wid  = tid >> 5;
    const int lane = tid & 31;
    const int g    = lane >> 2;   // 0..7
    const int tg   = lane & 3;    // 0..3

    const int th_i = tile >> 2;
    const int tw_i = tile & 3;

    // ---- the 4 kv tiles in the clamped window ----
    const int chc = min(max(th_i, 1), NTH - 1);
    const int cwc = min(max(tw_i, 1), NTW - 1);
    int kvt[4];
    kvt[0] = (chc - 1) * NTW + (cwc - 1);
    kvt[1] = (chc - 1) * NTW + cwc;
    kvt[2] = chc * NTW + (cwc - 1);
    kvt[3] = chc * NTW + cwc;

    // ---- query rows for this lane's fragments ----
    const int qi0 = wid * 16 + g;       // rows 0..7 of m-tile
    const int qi1 = qi0 + 8;            // rows 8..15
    const int sq0 = (th_i * 8 + (qi0 >> 4)) * 64 + tw_i * 16 + (qi0 & 15);
    const int sq1 = (th_i * 8 + (qi1 >> 4)) * 64 + tw_i * 16 + (qi1 & 15);
    const size_t qrow0 = ((size_t)(b * Ss + sq0)) * Dd + h * HDd;
    const size_t qrow1 = ((size_t)(b * Ss + sq1)) * Dd + h * HDd;

    // Q fragments: 8 k-steps x 4 regs (tf32, pre-scaled)
    uint32_t qa[8][4];
#pragma unroll
    for (int kq = 0; kq < 8; kq++) {
        qa[kq][0] = tf32_bits(Q[qrow0 + 8 * kq + tg] * SCALE);
        qa[kq][1] = tf32_bits(Q[qrow1 + 8 * kq + tg] * SCALE);
        qa[kq][2] = tf32_bits(Q[qrow0 + 8 * kq + tg + 4] * SCALE);
        qa[kq][3] = tf32_bits(Q[qrow1 + 8 * kq + tg + 4] * SCALE);
    }

    // online-softmax state (rows qi0 / qi1); l held as per-lane partials
    float m0 = -1e30f, m1 = -1e30f, l0 = 0.f, l1 = 0.f;
    float oacc[8][4];
#pragma unroll
    for (int j = 0; j < 8; j++)
#pragma unroll
        for (int c = 0; c < 4; c++) oacc[j][c] = 0.f;

    for (int cidx = 0; cidx < 8; cidx++) {
        const int ktile = kvt[cidx >> 1];
        const int half  = cidx & 1;
        const int kth = ktile >> 2;
        const int ktw = ktile & 3;

        __syncthreads();
        // ---- fill K,V chunk (64 keys x 64 dims), RNA tf32 ----
        for (int idx = tid; idx < 64 * 16; idx += 256) {
            int row = idx >> 4;         // key row in chunk
            int c4  = (idx & 15) * 4;   // hd offset
            int jj  = half * 64 + row;  // token within kv tile
            int rr  = jj >> 4;
            int cc  = jj & 15;
            int skv = (kth * 8 + rr) * 64 + (ktw * 16 + cc);
            size_t base = ((size_t)(b * Ss + skv)) * Dd + h * HDd + c4;
            float4 kv = *reinterpret_cast<const float4*>(Kb + base);
            float4 vv = *reinterpret_cast<const float4*>(Vb + base);
            *reinterpret_cast<float4*>(&Ks[row * KS_STRIDE + c4]) =
                make_float4(to_tf32(kv.x), to_tf32(kv.y), to_tf32(kv.z), to_tf32(kv.w));
            *reinterpret_cast<float4*>(&Vs[row * VS_STRIDE + c4]) =
                make_float4(to_tf32(vv.x), to_tf32(vv.y), to_tf32(vv.z), to_tf32(vv.w));
        }
        __syncthreads();

        // ---- S = Q K^T : sacc[jn] covers keys [8jn, 8jn+8) ----
        float sacc[8][4];
#pragma unroll
        for (int j = 0; j < 8; j++)
#pragma unroll
            for (int c = 0; c < 4; c++) sacc[j][c] = 0.f;

#pragma unroll
        for (int kq = 0; kq < 8; kq++) {
#pragma unroll
            for (int jn = 0; jn < 8; jn++) {
                uint32_t b0 = __float_as_uint(Ks[(8 * jn + g) * KS_STRIDE + 8 * kq + tg]);
                uint32_t b1 = __float_as_uint(Ks[(8 * jn + g) * KS_STRIDE + 8 * kq + tg + 4]);
                asm volatile(
                    "mma.sync.aligned.m16n8k8.row.col.f32.tf32.tf32.f32 "
                    "{%0,%1,%2,%3},{%4,%5,%6,%7},{%8,%9},{%0,%1,%2,%3};"
                    : "+f"(sacc[jn][0]), "+f"(sacc[jn][1]),
                      "+f"(sacc[jn][2]), "+f"(sacc[jn][3])
                    : "r"(qa[kq][0]), "r"(qa[kq][1]),
                      "r"(qa[kq][2]), "r"(qa[kq][3]),
                      "r"(b0), "r"(b1));
            }
        }

        // ---- online softmax in accumulator layout ----
        float mx0 = -1e30f, mx1 = -1e30f;
#pragma unroll
        for (int j = 0; j < 8; j++) {
            mx0 = fmaxf(mx0, fmaxf(sacc[j][0], sacc[j][1]));
            mx1 = fmaxf(mx1, fmaxf(sacc[j][2], sacc[j][3]));
        }
        mx0 = fmaxf(mx0, __shfl_xor_sync(0xffffffffu, mx0, 1));
        mx0 = fmaxf(mx0, __shfl_xor_sync(0xffffffffu, mx0, 2));
        mx1 = fmaxf(mx1, __shfl_xor_sync(0xffffffffu, mx1, 1));
        mx1 = fmaxf(mx1, __shfl_xor_sync(0xffffffffu, mx1, 2));

        float mn0 = fmaxf(m0, mx0);
        float mn1 = fmaxf(m1, mx1);
        float r0 = __expf(m0 - mn0);
        float r1 = __expf(m1 - mn1);
        m0 = mn0; m1 = mn1;
        l0 *= r0; l1 *= r1;
#pragma unroll
        for (int j = 0; j < 8; j++) {
            oacc[j][0] *= r0; oacc[j][1] *= r0;
            oacc[j][2] *= r1; oacc[j][3] *= r1;
        }
        // p = exp(s - m), accumulate l, convert to tf32 in place
#pragma unroll
        for (int j = 0; j < 8; j++) {
            float p0 = __expf(sacc[j][0] - m0);
            float p1 = __expf(sacc[j][1] - m0);
            float p2 = __expf(sacc[j][2] - m1);
            float p3 = __expf(sacc[j][3] - m1);
            l0 += p0 + p1;
            l1 += p2 + p3;
            sacc[j][0] = to_tf32(p0);
            sacc[j][1] = to_tf32(p1);
            sacc[j][2] = to_tf32(p2);
            sacc[j][3] = to_tf32(p3);
        }

        // ---- O += P V ----
        const int src0 = (lane & ~3) | (tg >> 1);
        const int src1 = src0 + 2;
#pragma unroll
        for (int kk = 0; kk < 8; kk++) {
            // acc layout (cols 2t,2t+1) -> A-frag layout (cols t, t+4)
            float x0 = __shfl_sync(0xffffffffu, sacc[kk][0], src0);
            float x1 = __shfl_sync(0xffffffffu, sacc[kk][1], src0);
            float y0 = __shfl_sync(0xffffffffu, sacc[kk][0], src1);
            float y1 = __shfl_sync(0xffffffffu, sacc[kk][1], src1);
            float z0 = __shfl_sync(0xffffffffu, sacc[kk][2], src0);
            float z1 = __shfl_sync(0xffffffffu, sacc[kk][3], src0);
            float w0 = __shfl_sync(0xffffffffu, sacc[kk][2], src1);
            float w1 = __shfl_sync(0xffffffffu, sacc[kk][3], src1);
            uint32_t pa0 = __float_as_uint((tg & 1) ? x1 : x0);
            uint32_t pa1 = __float_as_uint((tg & 1) ? z1 : z0);
            uint32_t pa2 = __float_as_uint((tg & 1) ? y1 : y0);
            uint32_t pa3 = __float_as_uint((tg & 1) ? w1 : w0);
#pragma unroll
            for (int jn = 0; jn < 8; jn++) {
                uint32_t vb0 = __float_as_uint(Vs[(8 * kk + tg) * VS_STRIDE + 8 * jn + g]);
                uint32_t vb1 = __float_as_uint(Vs[(8 * kk + tg + 4) * VS_STRIDE + 8 * jn + g]);
                asm volatile(
                    "mma.sync.aligned.m16n8k8.row.col.f32.tf32.tf32.f32 "
                    "{%0,%1,%2,%3},{%4,%5,%6,%7},{%8,%9},{%0,%1,%2,%3};"
                    : "+f"(oacc[jn][0]), "+f"(oacc[jn][1]),
                      "+f"(oacc[jn][2]), "+f"(oacc[jn][3])
                    : "r"(pa0), "r"(pa1), "r"(pa2), "r"(pa3),
                      "r"(vb0), "r"(vb1));
            }
        }
    }

    // ---- epilogue: reduce l across quad, normalize, store ----
    l0 += __shfl_xor_sync(0xffffffffu, l0, 1);
    l0 += __shfl_xor_sync(0xffffffffu, l0, 2);
    l1 += __shfl_xor_sync(0xffffffffu, l1, 1);
    l1 += __shfl_xor_sync(0xffffffffu, l1, 2);
    const float inv0 = 1.f / l0;
    const float inv1 = 1.f / l1;

    float* orow0 = (float*)(O + qrow0);
    float* orow1 = (float*)(O + qrow1);
#pragma unroll
    for (int jn = 0; jn < 8; jn++) {
        int vd = 8 * jn + 2 * tg;
        *reinterpret_cast<float2*>(orow0 + vd) =
            make_float2(oacc[jn][0] * inv0, oacc[jn][1] * inv0);
        *reinterpret_cast<float2*>(orow1 + vd) =
            make_float2(oacc[jn][2] * inv1, oacc[jn][3] * inv1);
    }
}

// ---------------- launch ----------------
extern "C" void kernel_launch(void* const* d_in, const int* in_sizes, int n_in,
                              void* d_out, int out_size)
{
    const float* X  = (const float*)d_in[0];
    const float* Wq = (const float*)d_in[1];
    const float* Wk = (const float*)d_in[2];
    const float* Wv = (const float*)d_in[3];
    const float* Wo = (const float*)d_in[4];
    float* out = (float*)d_out;

    float *Qp, *Kp, *Vp, *Op;
    cudaGetSymbolAddress((void**)&Qp, g_Q);
    cudaGetSymbolAddress((void**)&Kp, g_K);
    cudaGetSymbolAddress((void**)&Vp, g_V);
    cudaGetSymbolAddress((void**)&Op, g_O);

    dim3 gg(Dd / BN, MM / BM);   // (16, 64)
    tf32_gemm_kernel<<<gg, 256>>>(X, Wq, Qp, MM, Dd, Dd);
    tf32_gemm_kernel<<<gg, 256>>>(X, Wk, Kp, MM, Dd, Dd);
    tf32_gemm_kernel<<<gg, 256>>>(X, Wv, Vp, MM, Dd, Dd);

    dim3 ga(Tt, Hh, Bb);         // (32, 32, 2)
    attn_mma_kernel<<<ga, 256>>>(Qp, Kp, Vp, Op);

    tf32_gemm_kernel<<<gg, 256>>>(Op, Wo, out, MM, Dd, Dd);
}

// round 6
// speedup vs baseline: 4.0338x; 1.7244x over previous
#include <cuda_runtime.h>
#include <stdint.h>

// ---------------- static geometry ----------------
#define Bb   2
#define Ss   4096
#define Dd   2048
#define Hh   32
#define HDd  64
#define Tt   32
#define NTH  8
#define NTW  4
#define SCALE 0.125f  // 1/sqrt(64)

#define MM   (Bb*Ss)  // 8192
#define DD   ((size_t)Dd * Dd)

// ---------------- scratch ----------------
__device__ float g_Q[(size_t)MM * Dd];
__device__ float g_K[(size_t)MM * Dd];
__device__ float g_V[(size_t)MM * Dd];
__device__ float g_O[(size_t)MM * Dd];
__device__ float g_Xc[(size_t)MM * Dd];   // tf32-rounded X
__device__ float g_Wt[4 * DD];            // transposed + tf32-rounded weights [N][K]

// ---------------- helpers ----------------
__device__ __forceinline__ uint32_t tf32_bits(float x) {
    uint32_t u;
    asm("cvt.rna.tf32.f32 %0, %1;" : "=r"(u) : "f"(x));
    return u;
}
__device__ __forceinline__ float to_tf32(float x) {
    return __uint_as_float(tf32_bits(x));
}
__device__ __forceinline__ uint32_t smem_u32(const void* p) {
    uint32_t a;
    asm("{ .reg .u64 t; cvta.to.shared.u64 t, %1; cvt.u32.u64 %0, t; }"
        : "=r"(a) : "l"(p));
    return a;
}
__device__ __forceinline__ void cp16(uint32_t dst, const void* src) {
    asm volatile("cp.async.cg.shared.global [%0], [%1], 16;"
                 :: "r"(dst), "l"(src) : "memory");
}
__device__ __forceinline__ void cp_commit() {
    asm volatile("cp.async.commit_group;" ::: "memory");
}
template<int N>
__device__ __forceinline__ void cp_wait() {
    asm volatile("cp.async.wait_group %0;" :: "n"(N) : "memory");
}

// ---------------- prep kernels ----------------
__global__ __launch_bounds__(1024) void cvt_x_kernel(
    const float4* __restrict__ in, float4* __restrict__ out, int n4)
{
    int i = blockIdx.x * blockDim.x + threadIdx.x;
    if (i < n4) {
        float4 v = in[i];
        out[i] = make_float4(to_tf32(v.x), to_tf32(v.y), to_tf32(v.z), to_tf32(v.w));
    }
}

__global__ __launch_bounds__(256) void transpose_cvt_kernel(
    const float* __restrict__ W, float* __restrict__ Wt)
{
    __shared__ float t[32][33];
    const int bx = blockIdx.x * 32;  // n
    const int by = blockIdx.y * 32;  // k
    const int tx = threadIdx.x, ty = threadIdx.y;  // 32x8
#pragma unroll
    for (int r = 0; r < 32; r += 8)
        t[ty + r][tx] = W[(size_t)(by + ty + r) * Dd + bx + tx];
    __syncthreads();
#pragma unroll
    for (int r = 0; r < 32; r += 8)
        Wt[(size_t)(bx + ty + r) * Dd + by + tx] = to_tf32(t[tx][ty + r]);
}

// ---------------- tf32 mma.sync GEMM with cp.async 3-stage pipeline ----------------
// C[M,2048] = A[M,2048] @ Bt^T, A row-major [M][K], Bt row-major [N][K],
// both already tf32(RNA)-rounded. CTA: 128x128 tile, 256 threads.
// Smem stage: As 128x32 + Bs 128x32 floats, XOR-swizzled 16B chunks.
#define GBK 32
#define STAGE_FLOATS (128 * GBK)                 // per operand
#define STAGE_BYTES  (2 * STAGE_FLOATS * 4)      // 32 KB (A then B)
#define NSTAGE 3
#define SMEM_GEMM_TOTAL (NSTAGE * STAGE_BYTES)   // 96 KB

__device__ __forceinline__ void gemm_fill_async(
    const float* __restrict__ A, const float* __restrict__ Bt,
    uint32_t sbase, int stage, int m0, int n0, int k0, int tid)
{
    const uint32_t sA = sbase + stage * STAGE_BYTES;
    const uint32_t sB = sA + STAGE_FLOATS * 4;
#pragma unroll
    for (int i = 0; i < 4; i++) {
        int idx = tid + i * 256;           // 0..1023
        int row = idx >> 3;                // 0..127
        int c   = idx & 7;                 // 16B chunk within row
        uint32_t phys = row * 128 + ((c ^ (row & 7)) << 4);
        cp16(sA + phys, &A [(size_t)(m0 + row) * Dd + k0 + c * 4]);
        cp16(sB + phys, &Bt[(size_t)(n0 + row) * Dd + k0 + c * 4]);
    }
}

__global__ __launch_bounds__(256, 2) void tf32_gemm_async_kernel(
    const float* __restrict__ A, const float* __restrict__ Wt,
    float* __restrict__ C0, float* __restrict__ C1, float* __restrict__ C2)
{
    extern __shared__ char smem[];
    const uint32_t sbase = smem_u32(smem);
    const int tid  = threadIdx.x;
    const int wid  = tid >> 5;
    const int lane = tid & 31;
    const int g    = lane >> 2;   // 0..7
    const int t    = lane & 3;    // 0..3
    const int n0 = blockIdx.x * 128;
    const int m0 = blockIdx.y * 128;
    const int z  = blockIdx.z;

    const float* Bt = Wt + (size_t)z * DD;
    float* C = (z == 0) ? C0 : ((z == 1) ? C1 : C2);

    const int warp_m = (wid & 3) * 32;
    const int warp_n = (wid >> 2) * 64;

    float acc[2][8][4];
#pragma unroll
    for (int i = 0; i < 2; i++)
#pragma unroll
        for (int j = 0; j < 8; j++)
#pragma unroll
            for (int c = 0; c < 4; c++) acc[i][j][c] = 0.f;

    // prologue: stages 0,1 in flight
    gemm_fill_async(A, Bt, sbase, 0, m0, n0, 0, tid);
    cp_commit();
    gemm_fill_async(A, Bt, sbase, 1, m0, n0, GBK, tid);
    cp_commit();

    const int NCH = Dd / GBK;  // 64
    // per-thread row offsets (floats) into a stage
    const int arow0 = (warp_m + g) * GBK;
    const int arow1 = (warp_m + g + 16) * GBK;   // wm=1 base rows handled below
    const int brow  = (warp_n + g) * GBK;

    for (int ch = 0; ch < NCH; ch++) {
        if (ch < NCH - 2) cp_wait<1>(); else cp_wait<0>();
        __syncthreads();

        if (ch + 2 < NCH) {
            gemm_fill_async(A, Bt, sbase, (ch + 2) % NSTAGE, m0, n0,
                            (ch + 2) * GBK, tid);
            cp_commit();
        }

        const float* As = reinterpret_cast<const float*>(
            smem + (ch % NSTAGE) * STAGE_BYTES);
        const float* Bs = As + STAGE_FLOATS;

#pragma unroll
        for (int kk = 0; kk < GBK; kk += 8) {
            // swizzled within-row float offsets for cols {kk+t, kk+t+4}
            const int off1 = (((kk >> 2) ^ g) << 2) + t;
            const int off2 = off1 ^ 4;

            uint32_t af[2][4];
#pragma unroll
            for (int wm = 0; wm < 2; wm++) {
                const int rb = (wm == 0) ? arow0 : arow1;
                af[wm][0] = __float_as_uint(As[rb + off1]);
                af[wm][1] = __float_as_uint(As[rb + 8 * GBK + off1]);
                af[wm][2] = __float_as_uint(As[rb + off2]);
                af[wm][3] = __float_as_uint(As[rb + 8 * GBK + off2]);
            }
            uint32_t bf[8][2];
#pragma unroll
            for (int wn = 0; wn < 8; wn++) {
                const int rb = brow + wn * 8 * GBK;
                bf[wn][0] = __float_as_uint(Bs[rb + off1]);
                bf[wn][1] = __float_as_uint(Bs[rb + off2]);
            }
#pragma unroll
            for (int wm = 0; wm < 2; wm++)
#pragma unroll
                for (int wn = 0; wn < 8; wn++) {
                    asm volatile(
                        "mma.sync.aligned.m16n8k8.row.col.f32.tf32.tf32.f32 "
                        "{%0,%1,%2,%3},{%4,%5,%6,%7},{%8,%9},{%0,%1,%2,%3};"
                        : "+f"(acc[wm][wn][0]), "+f"(acc[wm][wn][1]),
                          "+f"(acc[wm][wn][2]), "+f"(acc[wm][wn][3])
                        : "r"(af[wm][0]), "r"(af[wm][1]),
                          "r"(af[wm][2]), "r"(af[wm][3]),
                          "r"(bf[wn][0]), "r"(bf[wn][1]));
                }
        }
    }

    // epilogue: direct coalesced-enough float2 stores (full 32B sectors)
#pragma unroll
    for (int wm = 0; wm < 2; wm++) {
        const int mb = m0 + warp_m + wm * 16;
#pragma unroll
        for (int wn = 0; wn < 8; wn++) {
            const int nb = n0 + warp_n + wn * 8 + 2 * t;
            *reinterpret_cast<float2*>(&C[(size_t)(mb + g) * Dd + nb]) =
                make_float2(acc[wm][wn][0], acc[wm][wn][1]);
            *reinterpret_cast<float2*>(&C[(size_t)(mb + g + 8) * Dd + nb]) =
                make_float2(acc[wm][wn][2], acc[wm][wn][3]);
        }
    }
}

// ---------------- tensor-core block-sparse sliding-tile attention ----------------
#define KS_STRIDE 68
#define VS_STRIDE 72

__global__ __launch_bounds__(256, 2) void attn_mma_kernel(
    const float* __restrict__ Q, const float* __restrict__ Kb,
    const float* __restrict__ Vb, float* __restrict__ O)
{
    __shared__ float Ks[64 * KS_STRIDE];
    __shared__ float Vs[64 * VS_STRIDE];

    const int tile = blockIdx.x;
    const int h    = blockIdx.y;
    const int b    = blockIdx.z;
    const int tid  = threadIdx.x;
    const int wid  = tid >> 5;
    const int lane = tid & 31;
    const int g    = lane >> 2;
    const int tg   = lane & 3;

    const int th_i = tile >> 2;
    const int tw_i = tile & 3;

    const int chc = min(max(th_i, 1), NTH - 1);
    const int cwc = min(max(tw_i, 1), NTW - 1);
    int kvt[4];
    kvt[0] = (chc - 1) * NTW + (cwc - 1);
    kvt[1] = (chc - 1) * NTW + cwc;
    kvt[2] = chc * NTW + (cwc - 1);
    kvt[3] = chc * NTW + cwc;

    const int qi0 = wid * 16 + g;
    const int qi1 = qi0 + 8;
    const int sq0 = (th_i * 8 + (qi0 >> 4)) * 64 + tw_i * 16 + (qi0 & 15);
    const int sq1 = (th_i * 8 + (qi1 >> 4)) * 64 + tw_i * 16 + (qi1 & 15);
    const size_t qrow0 = ((size_t)(b * Ss + sq0)) * Dd + h * HDd;
    const size_t qrow1 = ((size_t)(b * Ss + sq1)) * Dd + h * HDd;

    uint32_t qa[8][4];
#pragma unroll
    for (int kq = 0; kq < 8; kq++) {
        qa[kq][0] = tf32_bits(Q[qrow0 + 8 * kq + tg] * SCALE);
        qa[kq][1] = tf32_bits(Q[qrow1 + 8 * kq + tg] * SCALE);
        qa[kq][2] = tf32_bits(Q[qrow0 + 8 * kq + tg + 4] * SCALE);
        qa[kq][3] = tf32_bits(Q[qrow1 + 8 * kq + tg + 4] * SCALE);
    }

    float m0 = -1e30f, m1 = -1e30f, l0 = 0.f, l1 = 0.f;
    float oacc[8][4];
#pragma unroll
    for (int j = 0; j < 8; j++)
#pragma unroll
        for (int c = 0; c < 4; c++) oacc[j][c] = 0.f;

    for (int cidx = 0; cidx < 8; cidx++) {
        const int ktile = kvt[cidx >> 1];
        const int half  = cidx & 1;
        const int kth = ktile >> 2;
        const int ktw = ktile & 3;

        __syncthreads();
        for (int idx = tid; idx < 64 * 16; idx += 256) {
            int row = idx >> 4;
            int c4  = (idx & 15) * 4;
            int jj  = half * 64 + row;
            int rr  = jj >> 4;
            int cc  = jj & 15;
            int skv = (kth * 8 + rr) * 64 + (ktw * 16 + cc);
            size_t base = ((size_t)(b * Ss + skv)) * Dd + h * HDd + c4;
            float4 kv = *reinterpret_cast<const float4*>(Kb + base);
            float4 vv = *reinterpret_cast<const float4*>(Vb + base);
            *reinterpret_cast<float4*>(&Ks[row * KS_STRIDE + c4]) =
                make_float4(to_tf32(kv.x), to_tf32(kv.y), to_tf32(kv.z), to_tf32(kv.w));
            *reinterpret_cast<float4*>(&Vs[row * VS_STRIDE + c4]) =
                make_float4(to_tf32(vv.x), to_tf32(vv.y), to_tf32(vv.z), to_tf32(vv.w));
        }
        __syncthreads();

        float sacc[8][4];
#pragma unroll
        for (int j = 0; j < 8; j++)
#pragma unroll
            for (int c = 0; c < 4; c++) sacc[j][c] = 0.f;

#pragma unroll
        for (int kq = 0; kq < 8; kq++) {
#pragma unroll
            for (int jn = 0; jn < 8; jn++) {
                uint32_t b0 = __float_as_uint(Ks[(8 * jn + g) * KS_STRIDE + 8 * kq + tg]);
                uint32_t b1 = __float_as_uint(Ks[(8 * jn + g) * KS_STRIDE + 8 * kq + tg + 4]);
                asm volatile(
                    "mma.sync.aligned.m16n8k8.row.col.f32.tf32.tf32.f32 "
                    "{%0,%1,%2,%3},{%4,%5,%6,%7},{%8,%9},{%0,%1,%2,%3};"
                    : "+f"(sacc[jn][0]), "+f"(sacc[jn][1]),
                      "+f"(sacc[jn][2]), "+f"(sacc[jn][3])
                    : "r"(qa[kq][0]), "r"(qa[kq][1]),
                      "r"(qa[kq][2]), "r"(qa[kq][3]),
                      "r"(b0), "r"(b1));
            }
        }

        float mx0 = -1e30f, mx1 = -1e30f;
#pragma unroll
        for (int j = 0; j < 8; j++) {
            mx0 = fmaxf(mx0, fmaxf(sacc[j][0], sacc[j][1]));
            mx1 = fmaxf(mx1, fmaxf(sacc[j][2], sacc[j][3]));
        }
        mx0 = fmaxf(mx0, __shfl_xor_sync(0xffffffffu, mx0, 1));
        mx0 = fmaxf(mx0, __shfl_xor_sync(0xffffffffu, mx0, 2));
        mx1 = fmaxf(mx1, __shfl_xor_sync(0xffffffffu, mx1, 1));
        mx1 = fmaxf(mx1, __shfl_xor_sync(0xffffffffu, mx1, 2));

        float mn0 = fmaxf(m0, mx0);
        float mn1 = fmaxf(m1, mx1);
        float r0 = __expf(m0 - mn0);
        float r1 = __expf(m1 - mn1);
        m0 = mn0; m1 = mn1;
        l0 *= r0; l1 *= r1;
#pragma unroll
        for (int j = 0; j < 8; j++) {
            oacc[j][0] *= r0; oacc[j][1] *= r0;
            oacc[j][2] *= r1; oacc[j][3] *= r1;
        }
#pragma unroll
        for (int j = 0; j < 8; j++) {
            float p0 = __expf(sacc[j][0] - m0);
            float p1 = __expf(sacc[j][1] - m0);
            float p2 = __expf(sacc[j][2] - m1);
            float p3 = __expf(sacc[j][3] - m1);
            l0 += p0 + p1;
            l1 += p2 + p3;
            sacc[j][0] = to_tf32(p0);
            sacc[j][1] = to_tf32(p1);
            sacc[j][2] = to_tf32(p2);
            sacc[j][3] = to_tf32(p3);
        }

        const int src0 = (lane & ~3) | (tg >> 1);
        const int src1 = src0 + 2;
#pragma unroll
        for (int kk = 0; kk < 8; kk++) {
            float x0 = __shfl_sync(0xffffffffu, sacc[kk][0], src0);
            float x1 = __shfl_sync(0xffffffffu, sacc[kk][1], src0);
            float y0 = __shfl_sync(0xffffffffu, sacc[kk][0], src1);
            float y1 = __shfl_sync(0xffffffffu, sacc[kk][1], src1);
            float z0 = __shfl_sync(0xffffffffu, sacc[kk][2], src0);
            float z1 = __shfl_sync(0xffffffffu, sacc[kk][3], src0);
            float w0 = __shfl_sync(0xffffffffu, sacc[kk][2], src1);
            float w1 = __shfl_sync(0xffffffffu, sacc[kk][3], src1);
            uint32_t pa0 = __float_as_uint((tg & 1) ? x1 : x0);
            uint32_t pa1 = __float_as_uint((tg & 1) ? z1 : z0);
            uint32_t pa2 = __float_as_uint((tg & 1) ? y1 : y0);
            uint32_t pa3 = __float_as_uint((tg & 1) ? w1 : w0);
#pragma unroll
            for (int jn = 0; jn < 8; jn++) {
                uint32_t vb0 = __float_as_uint(Vs[(8 * kk + tg) * VS_STRIDE + 8 * jn + g]);
                uint32_t vb1 = __float_as_uint(Vs[(8 * kk + tg + 4) * VS_STRIDE + 8 * jn + g]);
                asm volatile(
                    "mma.sync.aligned.m16n8k8.row.col.f32.tf32.tf32.f32 "
                    "{%0,%1,%2,%3},{%4,%5,%6,%7},{%8,%9},{%0,%1,%2,%3};"
                    : "+f"(oacc[jn][0]), "+f"(oacc[jn][1]),
                      "+f"(oacc[jn][2]), "+f"(oacc[jn][3])
                    : "r"(pa0), "r"(pa1), "r"(pa2), "r"(pa3),
                      "r"(vb0), "r"(vb1));
            }
        }
    }

    l0 += __shfl_xor_sync(0xffffffffu, l0, 1);
    l0 += __shfl_xor_sync(0xffffffffu, l0, 2);
    l1 += __shfl_xor_sync(0xffffffffu, l1, 1);
    l1 += __shfl_xor_sync(0xffffffffu, l1, 2);
    const float inv0 = 1.f / l0;
    const float inv1 = 1.f / l1;

    // write O tf32(RNA)-rounded so the final GEMM consumes valid tf32 bits
    float* orow0 = (float*)(O + qrow0);
    float* orow1 = (float*)(O + qrow1);
#pragma unroll
    for (int jn = 0; jn < 8; jn++) {
        int vd = 8 * jn + 2 * tg;
        *reinterpret_cast<float2*>(orow0 + vd) =
            make_float2(to_tf32(oacc[jn][0] * inv0), to_tf32(oacc[jn][1] * inv0));
        *reinterpret_cast<float2*>(orow1 + vd) =
            make_float2(to_tf32(oacc[jn][2] * inv1), to_tf32(oacc[jn][3] * inv1));
    }
}

// ---------------- launch ----------------
extern "C" void kernel_launch(void* const* d_in, const int* in_sizes, int n_in,
                              void* d_out, int out_size)
{
    const float* X  = (const float*)d_in[0];
    const float* Wq = (const float*)d_in[1];
    const float* Wk = (const float*)d_in[2];
    const float* Wv = (const float*)d_in[3];
    const float* Wo = (const float*)d_in[4];
    float* out = (float*)d_out;

    float *Qp, *Kp, *Vp, *Op, *Xc, *Wt;
    cudaGetSymbolAddress((void**)&Qp, g_Q);
    cudaGetSymbolAddress((void**)&Kp, g_K);
    cudaGetSymbolAddress((void**)&Vp, g_V);
    cudaGetSymbolAddress((void**)&Op, g_O);
    cudaGetSymbolAddress((void**)&Xc, g_Xc);
    cudaGetSymbolAddress((void**)&Wt, g_Wt);

    cudaFuncSetAttribute(tf32_gemm_async_kernel,
                         cudaFuncAttributeMaxDynamicSharedMemorySize, SMEM_GEMM_TOTAL);

    // prep: tf32-round X; transpose+round weights into [N][K]
    int n4 = (int)((size_t)MM * Dd / 4);
    cvt_x_kernel<<<(n4 + 1023) / 1024, 1024>>>((const float4*)X, (float4*)Xc, n4);
    dim3 tb(32, 8), tg2(64, 64);
    transpose_cvt_kernel<<<tg2, tb>>>(Wq, Wt + 0 * DD);
    transpose_cvt_kernel<<<tg2, tb>>>(Wk, Wt + 1 * DD);
    transpose_cvt_kernel<<<tg2, tb>>>(Wv, Wt + 2 * DD);
    transpose_cvt_kernel<<<tg2, tb>>>(Wo, Wt + 3 * DD);

    // fused Q/K/V projections: grid.z selects weight + destination
    dim3 gq(Dd / 128, MM / 128, 3);   // (16, 64, 3)
    tf32_gemm_async_kernel<<<gq, 256, SMEM_GEMM_TOTAL>>>(Xc, Wt, Qp, Kp, Vp);

    dim3 ga(Tt, Hh, Bb);
    attn_mma_kernel<<<ga, 256>>>(Qp, Kp, Vp, Op);

    // output projection (z=0 -> Wt+3*DD via pointer offset trick)
    dim3 gg(Dd / 128, MM / 128, 1);
    tf32_gemm_async_kernel<<<gg, 256, SMEM_GEMM_TOTAL>>>(Op, Wt + 3 * DD, out, out, out);
}